// round 14
// baseline (speedup 1.0000x reference)
#include <cuda_runtime.h>
#include <cuda_fp16.h>
#include <stdint.h>
#include <math.h>

#define SS 256
#define CC 128
#define HH 4
#define PP (SS*SS)
#define EPSV 1e-5f
#define SCALE_L2E 0.25501802f        /* (1/sqrt(32)) * log2(e) */
#define L2E 1.4426950408889634f

/* ---- scratch ----
   "permuted" = k-dim pair permutation pp(p) baked into the layout so that
   fp16 m16n8k16 fragments are single LDS.64 loads. */
__device__ __half g_h[PP*CC];      /* LN output, fp16, k-pairs permuted */
__device__ __half g_qh[PP*CC];     /* q (pre-scaled), permuted d-pairs */
__device__ __half g_kh[PP*CC];     /* k, permuted d-pairs */
__device__ __half g_vh[PP*CC];     /* v, natural layout */
__device__ float  g_g[PP*CC];      /* sigmoid(gate) */
__device__ __half g_oh[PP*CC];     /* gated o, permuted e-pairs */
__device__ float  g_bias[HH*PP];   /* [h][j*S + k], pre-scaled by log2(e) */
__device__ __half g_wtsh[5*16384]; /* fp16 weights, k-pairs permuted */

__device__ __forceinline__ int pp8(int p) {
    return (p & ~7) | ((p & 3) << 1) | ((p >> 2) & 1);
}
__device__ __forceinline__ float warp_sum(float v) {
    v += __shfl_xor_sync(0xffffffffu, v, 16);
    v += __shfl_xor_sync(0xffffffffu, v, 8);
    v += __shfl_xor_sync(0xffffffffu, v, 4);
    v += __shfl_xor_sync(0xffffffffu, v, 2);
    v += __shfl_xor_sync(0xffffffffu, v, 1);
    return v;
}
__device__ __forceinline__ float ex2(float x) {
    float r; asm("ex2.approx.ftz.f32 %0, %1;" : "=f"(r) : "f"(x)); return r;
}
__device__ __forceinline__ float rcpf(float x) {
    float r; asm("rcp.approx.ftz.f32 %0, %1;" : "=f"(r) : "f"(x)); return r;
}
__device__ __forceinline__ uint32_t smem_u32(const void* p) {
    uint32_t a;
    asm("{ .reg .u64 t; cvta.to.shared.u64 t, %1; cvt.u32.u64 %0, t; }" : "=r"(a) : "l"(p));
    return a;
}
/* fp16 m16n8k16 */
__device__ __forceinline__ void mma16h(float* c, const uint32_t* a,
                                       uint32_t b0, uint32_t b1) {
    asm volatile(
        "mma.sync.aligned.m16n8k16.row.col.f32.f16.f16.f32 "
        "{%0,%1,%2,%3},{%4,%5,%6,%7},{%8,%9},{%0,%1,%2,%3};"
        : "+f"(c[0]), "+f"(c[1]), "+f"(c[2]), "+f"(c[3])
        : "r"(a[0]), "r"(a[1]), "r"(a[2]), "r"(a[3]), "r"(b0), "r"(b1));
}
#define CP16(dst, src) \
    asm volatile("cp.async.cg.shared.global [%0], [%1], 16;" :: "r"(dst), "l"(src))
#define CP_COMMIT() asm volatile("cp.async.commit_group;" ::: "memory")
#define CP_WAIT(n)  asm volatile("cp.async.wait_group %0;" :: "n"(n) : "memory")

/* =============== LayerNorm + pair-bias + weight prep =============== */
__global__ void ln_bias_kernel(const float* __restrict__ x,
                               const float* __restrict__ w,
                               const float* __restrict__ b,
                               const float* __restrict__ wb,
                               const float* __restrict__ wq,
                               const float* __restrict__ wk,
                               const float* __restrict__ wv,
                               const float* __restrict__ wg,
                               const float* __restrict__ wo) {
    int row  = blockIdx.x * 8 + (threadIdx.x >> 5);
    int lane = threadIdx.x & 31;
    const float4* xr = (const float4*)(x + (size_t)row * CC);
    float4 v = xr[lane];
    float mu = warp_sum(v.x + v.y + v.z + v.w) * (1.f / 128.f);
    float dx = v.x - mu, dy = v.y - mu, dz = v.z - mu, dw = v.w - mu;
    float var = warp_sum(dx*dx + dy*dy + dz*dz + dw*dw) * (1.f / 128.f);
    float rs = rsqrtf(var + EPSV);
    float4 wv4 = ((const float4*)w)[lane];
    float4 bv = ((const float4*)b)[lane];
    float4 o;
    o.x = dx * rs * wv4.x + bv.x;
    o.y = dy * rs * wv4.y + bv.y;
    o.z = dz * rs * wv4.z + bv.z;
    o.w = dw * rs * wv4.w + bv.w;

    /* store fp16, k-pair permuted (lane holds pairs 2*lane, 2*lane+1) */
    __half2* hr = (__half2*)(g_h + (size_t)row * CC);
    hr[pp8(2*lane)]     = __floats2half2_rn(o.x, o.y);
    hr[pp8(2*lane + 1)] = __floats2half2_rn(o.z, o.w);

    #pragma unroll
    for (int hh = 0; hh < HH; ++hh) {
        float4 wbv = ((const float4*)(wb + hh * CC))[lane];
        float p = o.x*wbv.x + o.y*wbv.y + o.z*wbv.z + o.w*wbv.w;
        p = warp_sum(p);
        if (lane == hh) g_bias[(size_t)hh * PP + row] = p * L2E;
    }

    /* first 64 blocks prep fp16 permuted weights (16384 elems each) */
    if (blockIdx.x < 64) {
        int idx = blockIdx.x * 256 + threadIdx.x;
        int n = idx >> 7, k = idx & 127;
        int d = n * 128 + pp8(k >> 1) * 2 + (k & 1);
        g_wtsh[d]             = __float2half(wq[idx] * SCALE_L2E);
        g_wtsh[16384 + d]     = __float2half(wk[idx]);
        g_wtsh[2*16384 + d]   = __float2half(wv[idx]);
        g_wtsh[3*16384 + d]   = __float2half(wg[idx]);
        g_wtsh[4*16384 + d]   = __float2half(wo[idx]);
    }
}

/* ====== fp16 GEMM: 128x128 tile, 2-stage k64 cp.async, warp 64x32 ====== */
#define GSH 80                         /* smem stride in halves */
#define GAH (128*GSH)                  /* halves per A (or W) region */
#define GSTAGEH (2*GAH)                /* halves per stage */
#define GEMM_SMEM (2 * GSTAGEH * 2)    /* 81920 B */

__global__ void __launch_bounds__(256, 2)
gemm_tc(const __half* __restrict__ Ah, float* __restrict__ OutO, int outp) {
    extern __shared__ __align__(16) char smc[];
    uint32_t sb = smem_u32(smc);
    int wsel = outp ? 4 : (blockIdx.x & 3);
    int m0   = (outp ? blockIdx.x : (blockIdx.x >> 2)) * 128;
    const __half* Wh = g_wtsh + (size_t)wsel * 16384;

    int tid = threadIdx.x;
    int wid = tid >> 5, lane = tid & 31;
    int g = lane >> 2, t = lane & 3;
    int wm = wid >> 2, wn = wid & 3;   /* 2 x 4 warp grid, warp tile 64x32 */

    float acc[4][4][4];
    #pragma unroll
    for (int i = 0; i < 4; ++i)
        #pragma unroll
        for (int j = 0; j < 4; ++j)
            #pragma unroll
            for (int e = 0; e < 4; ++e) acc[i][j][e] = 0.f;

    #define LDCHUNK(c, s) do {                                              \
        uint32_t dA = sb + (uint32_t)((s) * GSTAGEH) * 2;                   \
        uint32_t dW = dA + (uint32_t)GAH * 2;                               \
        _Pragma("unroll")                                                   \
        for (int it = 0; it < 4; ++it) {                                    \
            int idx = tid + it * 256;                                       \
            int r = idx >> 3, ch = idx & 7;                                 \
            CP16(dA + (uint32_t)(r * GSH + ch * 8) * 2,                     \
                 &Ah[(size_t)(m0 + r) * CC + (c) * 64 + ch * 8]);           \
            CP16(dW + (uint32_t)(r * GSH + ch * 8) * 2,                     \
                 &Wh[(size_t)r * CC + (c) * 64 + ch * 8]);                  \
        }                                                                   \
    } while (0)

    #define COMPUTE(s) do {                                                 \
        const __half* As = (const __half*)smc + (s) * GSTAGEH;              \
        const __half* Ws = As + GAH;                                        \
        _Pragma("unroll")                                                   \
        for (int kk = 0; kk < 4; ++kk) {                                    \
            uint32_t af[4][4];                                              \
            _Pragma("unroll")                                               \
            for (int mt = 0; mt < 4; ++mt) {                                \
                uint2 u0 = *(const uint2*)&As[(wm*64 + mt*16 + g) * GSH + kk*16 + 4*t]; \
                uint2 u1 = *(const uint2*)&As[(wm*64 + mt*16 + g + 8) * GSH + kk*16 + 4*t]; \
                af[mt][0] = u0.x; af[mt][1] = u1.x;                         \
                af[mt][2] = u0.y; af[mt][3] = u1.y;                         \
            }                                                               \
            _Pragma("unroll")                                               \
            for (int nt = 0; nt < 4; ++nt) {                                \
                uint2 z = *(const uint2*)&Ws[(wn*32 + nt*8 + g) * GSH + kk*16 + 4*t]; \
                _Pragma("unroll")                                           \
                for (int mt = 0; mt < 4; ++mt)                              \
                    mma16h(acc[mt][nt], af[mt], z.x, z.y);                  \
            }                                                               \
        }                                                                   \
    } while (0)

    LDCHUNK(0, 0); CP_COMMIT();
    LDCHUNK(1, 1); CP_COMMIT();
    CP_WAIT(1); __syncthreads();
    COMPUTE(0);
    CP_WAIT(0); __syncthreads();
    COMPUTE(1);

    /* epilogue */
    #pragma unroll
    for (int mt = 0; mt < 4; ++mt) {
        int row0 = m0 + wm*64 + mt*16 + g;
        #pragma unroll
        for (int nt = 0; nt < 4; ++nt) {
            float a0 = acc[mt][nt][0], a1 = acc[mt][nt][1];
            float a2 = acc[mt][nt][2], a3 = acc[mt][nt][3];
            int coln = wn*32 + nt*8 + 2*t;           /* natural col */
            int ppi  = pp8(wn*16 + 4*nt + t);        /* permuted pair idx */
            size_t i0n = (size_t)row0 * CC;
            size_t i1n = (size_t)(row0 + 8) * CC;
            if (outp) {
                *(float2*)&OutO[i0n + coln] = make_float2(a0, a1);
                *(float2*)&OutO[i1n + coln] = make_float2(a2, a3);
            } else if (wsel == 0) {
                *(__half2*)&g_qh[i0n + ppi*2] = __floats2half2_rn(a0, a1);
                *(__half2*)&g_qh[i1n + ppi*2] = __floats2half2_rn(a2, a3);
            } else if (wsel == 1) {
                *(__half2*)&g_kh[i0n + ppi*2] = __floats2half2_rn(a0, a1);
                *(__half2*)&g_kh[i1n + ppi*2] = __floats2half2_rn(a2, a3);
            } else if (wsel == 2) {
                *(__half2*)&g_vh[i0n + coln] = __floats2half2_rn(a0, a1);
                *(__half2*)&g_vh[i1n + coln] = __floats2half2_rn(a2, a3);
            } else {
                float s0 = rcpf(1.f + ex2(-a0 * L2E));
                float s1 = rcpf(1.f + ex2(-a1 * L2E));
                float s2 = rcpf(1.f + ex2(-a2 * L2E));
                float s3 = rcpf(1.f + ex2(-a3 * L2E));
                *(float2*)&g_g[i0n + coln] = make_float2(s0, s1);
                *(float2*)&g_g[i1n + coln] = make_float2(s2, s3);
            }
        }
    }
    #undef LDCHUNK
    #undef COMPUTE
}

/* =============== attention: fp16 scores + fp16 2-term PV ==================
   block=(i,h); 8 warps x 32 q-rows; 8 k-chunks of 32.
   Q/K fp16 (permuted d-pairs) in smem, stride 48 halves. */
#define KSTH 48
#define KBYTES (256*KSTH*2)       /* 24576 */
#define VTP 136
#define ATTN_SMEM (2*KBYTES)      /* 49152 B */

__global__ void __launch_bounds__(256, 2) attn_tc() {
    extern __shared__ __align__(16) char smc[];
    uint32_t sb = smem_u32(smc);
    __half* Ksm = (__half*)smc;
    __half* Usm = (__half*)(smc + KBYTES);   /* Q stage, then Vt */
    int tid = threadIdx.x;
    int wid = tid >> 5, lane = tid & 31;
    int g = lane >> 2, t = lane & 3;
    int i = blockIdx.x, h = blockIdx.y;
    size_t base = ((size_t)i * SS) * CC + (size_t)h * 32;

    /* stage 1: cp.async K and Q rows (64 B each) */
    {
        int r = tid;
        uint32_t kd = sb + (uint32_t)(r * KSTH) * 2;
        uint32_t qd = sb + (uint32_t)KBYTES + (uint32_t)(r * KSTH) * 2;
        const __half* ks = &g_kh[base + (size_t)r * CC];
        const __half* qs = &g_qh[base + (size_t)r * CC];
        #pragma unroll
        for (int ch = 0; ch < 4; ++ch) {
            CP16(kd + ch * 16, ks + ch * 8);
            CP16(qd + ch * 16, qs + ch * 8);
        }
        CP_COMMIT();
    }
    /* V row to registers (natural layout) */
    unsigned short sv[32];
    {
        const uint4* vg = (const uint4*)(g_vh + base + (size_t)tid * CC);
        *(uint4*)&sv[0]  = vg[0];
        *(uint4*)&sv[8]  = vg[1];
        *(uint4*)&sv[16] = vg[2];
        *(uint4*)&sv[24] = vg[3];
    }
    CP_WAIT(0);
    __syncthreads();

    /* stage 2: Q fragments to registers (2 m-tiles, 2 k16-groups) */
    int wrow = wid * 32;
    uint32_t qa[2][2][4];
    #pragma unroll
    for (int mt = 0; mt < 2; ++mt)
        #pragma unroll
        for (int kk = 0; kk < 2; ++kk) {
            uint2 u0 = *(const uint2*)&Usm[(wrow + mt*16 + g) * KSTH + kk*16 + 4*t];
            uint2 u1 = *(const uint2*)&Usm[(wrow + mt*16 + g + 8) * KSTH + kk*16 + 4*t];
            qa[mt][kk][0] = u0.x; qa[mt][kk][1] = u1.x;
            qa[mt][kk][2] = u0.y; qa[mt][kk][3] = u1.y;
        }
    __syncthreads();

    /* stage 3: Vt fp16 in U region, kseq-pair-permuted */
    {
        unsigned short* vt = (unsigned short*)Usm;
        int pr = tid >> 1, hs = tid & 1;
        int ppr = (pr & ~7) | ((pr & 3) * 2 + ((pr >> 2) & 1));
        #pragma unroll
        for (int d = 0; d < 32; ++d)
            vt[(d * VTP + ppr) * 2 + hs] = sv[d];
    }
    __syncthreads();

    const uint32_t* vtw = (const uint32_t*)Usm;
    const float* bh = g_bias + (size_t)h * PP;

    float pv[2][4][4];
    #pragma unroll
    for (int mt = 0; mt < 2; ++mt)
        #pragma unroll
        for (int nt = 0; nt < 4; ++nt)
            #pragma unroll
            for (int e = 0; e < 4; ++e) pv[mt][nt][e] = 0.f;
    float lsum[2][2] = {{0.f,0.f},{0.f,0.f}};

    for (int c = 0; c < 8; ++c) {
        /* scores (fp16 k16): 32 j x 32 k */
        float sacc[2][4][4];
        #pragma unroll
        for (int mt = 0; mt < 2; ++mt)
            #pragma unroll
            for (int nt = 0; nt < 4; ++nt)
                #pragma unroll
                for (int e = 0; e < 4; ++e) sacc[mt][nt][e] = 0.f;
        #pragma unroll
        for (int nt = 0; nt < 4; ++nt)
            #pragma unroll
            for (int kk = 0; kk < 2; ++kk) {
                uint2 z = *(const uint2*)&Ksm[(c*32 + nt*8 + g) * KSTH + kk*16 + 4*t];
                mma16h(sacc[0][nt], qa[0][kk], z.x, z.y);
                mma16h(sacc[1][nt], qa[1][kk], z.x, z.y);
            }

        /* softmax + pack P hi/lo fp16 A-fragments */
        uint32_t ah[2][2][4], al[2][2][4];
        #pragma unroll
        for (int mt = 0; mt < 2; ++mt) {
            int j = wrow + mt*16 + g;
            #pragma unroll
            for (int kk2 = 0; kk2 < 2; ++kk2)
                #pragma unroll
                for (int qn = 0; qn < 2; ++qn) {
                    int nt = kk2*2 + qn;
                    int kcol = c*32 + nt*8 + 2*t;
                    float2 b0 = *(const float2*)&bh[(size_t)j * SS + kcol];
                    float2 b1 = *(const float2*)&bh[(size_t)(j+8) * SS + kcol];
                    float p0 = ex2(sacc[mt][nt][0] + b0.x);
                    float p1 = ex2(sacc[mt][nt][1] + b0.y);
                    float p2 = ex2(sacc[mt][nt][2] + b1.x);
                    float p3 = ex2(sacc[mt][nt][3] + b1.y);
                    lsum[mt][0] += p0 + p1;
                    lsum[mt][1] += p2 + p3;
                    __half2 H01 = __floats2half2_rn(p0, p1);
                    __half2 H23 = __floats2half2_rn(p2, p3);
                    ah[mt][kk2][qn*2+0] = *(uint32_t*)&H01;
                    ah[mt][kk2][qn*2+1] = *(uint32_t*)&H23;
                    __half2 L01 = __floats2half2_rn(p0 - __low2float(H01),
                                                    p1 - __high2float(H01));
                    __half2 L23 = __floats2half2_rn(p2 - __low2float(H23),
                                                    p3 - __high2float(H23));
                    al[mt][kk2][qn*2+0] = *(uint32_t*)&L01;
                    al[mt][kk2][qn*2+1] = *(uint32_t*)&L23;
                }
        }

        /* PV (fp16 k16, 2 terms), V fragments shared across both m-tiles */
        #pragma unroll
        for (int kk2 = 0; kk2 < 2; ++kk2)
            #pragma unroll
            for (int nt = 0; nt < 4; ++nt) {
                uint2 b = *(const uint2*)&vtw[(nt*8 + g) * VTP + c*16 + kk2*8 + 2*t];
                #pragma unroll
                for (int mt = 0; mt < 2; ++mt) {
                    mma16h(pv[mt][nt], ah[mt][kk2], b.x, b.y);
                    mma16h(pv[mt][nt], al[mt][kk2], b.x, b.y);
                }
            }
    }

    /* reduce l over quad lanes, gate, store fp16 permuted into g_oh */
    float inv[2][2];
    #pragma unroll
    for (int mt = 0; mt < 2; ++mt)
        #pragma unroll
        for (int rh = 0; rh < 2; ++rh) {
            float l = lsum[mt][rh];
            l += __shfl_xor_sync(0xffffffffu, l, 1);
            l += __shfl_xor_sync(0xffffffffu, l, 2);
            inv[mt][rh] = rcpf(l);
        }
    #pragma unroll
    for (int mt = 0; mt < 2; ++mt) {
        int j = wrow + mt*16 + g;
        size_t r0 = base + (size_t)j * CC;
        size_t r1 = base + (size_t)(j+8) * CC;
        #pragma unroll
        for (int nt = 0; nt < 4; ++nt) {
            int col = nt*8 + 2*t;                 /* within-head natural */
            int ppi = pp8(4*nt + t);              /* within-head permuted pair */
            float2 s0 = *(const float2*)&g_g[r0 + col];
            float2 s1 = *(const float2*)&g_g[r1 + col];
            *(__half2*)&g_oh[r0 + ppi*2] =
                __floats2half2_rn(pv[mt][nt][0]*inv[mt][0]*s0.x,
                                  pv[mt][nt][1]*inv[mt][0]*s0.y);
            *(__half2*)&g_oh[r1 + ppi*2] =
                __floats2half2_rn(pv[mt][nt][2]*inv[mt][1]*s1.x,
                                  pv[mt][nt][3]*inv[mt][1]*s1.y);
        }
    }
}

extern "C" void kernel_launch(void* const* d_in, const int* in_sizes, int n_in,
                              void* d_out, int out_size) {
    (void)in_sizes; (void)n_in; (void)out_size;
    const float* x      = (const float*)d_in[0];
    const float* ln_w   = (const float*)d_in[1];
    const float* ln_b   = (const float*)d_in[2];
    const float* w_bias = (const float*)d_in[3];
    const float* w_q    = (const float*)d_in[4];
    const float* w_k    = (const float*)d_in[5];
    const float* w_v    = (const float*)d_in[6];
    const float* w_g    = (const float*)d_in[7];
    const float* w_o    = (const float*)d_in[8];
    float* out = (float*)d_out;

    __half *ph, *po;
    cudaGetSymbolAddress((void**)&ph, g_h);
    cudaGetSymbolAddress((void**)&po, g_oh);

    cudaFuncSetAttribute(gemm_tc,
                         cudaFuncAttributeMaxDynamicSharedMemorySize, GEMM_SMEM);
    cudaFuncSetAttribute(attn_tc,
                         cudaFuncAttributeMaxDynamicSharedMemorySize, ATTN_SMEM);

    ln_bias_kernel<<<PP/8, 256>>>(x, ln_w, ln_b, w_bias,
                                  w_q, w_k, w_v, w_g, w_o);

    /* fused q,k,v,g projections; wsel = blockIdx.x & 3 (A tiles L2-shared) */
    gemm_tc<<<(PP/128) * 4, 256, GEMM_SMEM>>>(ph, nullptr, 0);

    attn_tc<<<dim3(SS, HH), 256, ATTN_SMEM>>>();

    /* output projection (o already gated, fp16 permuted) */
    gemm_tc<<<PP/128, 256, GEMM_SMEM>>>(po, out, 1);
}

// round 15
// speedup vs baseline: 1.3588x; 1.3588x over previous
#include <cuda_runtime.h>
#include <cuda_fp16.h>
#include <stdint.h>
#include <math.h>

#define SS 256
#define CC 128
#define HH 4
#define PP (SS*SS)
#define EPSV 1e-5f
#define SCALE_L2E 0.25501802f        /* (1/sqrt(32)) * log2(e) */
#define L2E 1.4426950408889634f

/* ---- scratch ----
   "permuted" = k-dim pair permutation pp8(p) baked into the layout so that
   fp16 m16n8k16 fragments are single LDS.64 loads. */
__device__ __half g_h[PP*CC];      /* LN output, fp16, k-pairs permuted */
__device__ __half g_qh[PP*CC];     /* q (pre-scaled), permuted d-pairs */
__device__ __half g_kh[PP*CC];     /* k, permuted d-pairs */
__device__ __half g_vh[PP*CC];     /* v, natural layout */
__device__ float  g_g[PP*CC];      /* sigmoid(gate) */
__device__ __half g_oh[PP*CC];     /* gated o, permuted e-pairs */
__device__ float  g_bias[HH*PP];   /* [h][j*S + k], pre-scaled by log2(e) */
__device__ __half g_wtsh[5*16384]; /* fp16 weights, k-pairs permuted */

__device__ __forceinline__ int pp8(int p) {
    return (p & ~7) | ((p & 3) << 1) | ((p >> 2) & 1);
}
__device__ __forceinline__ float warp_sum(float v) {
    v += __shfl_xor_sync(0xffffffffu, v, 16);
    v += __shfl_xor_sync(0xffffffffu, v, 8);
    v += __shfl_xor_sync(0xffffffffu, v, 4);
    v += __shfl_xor_sync(0xffffffffu, v, 2);
    v += __shfl_xor_sync(0xffffffffu, v, 1);
    return v;
}
__device__ __forceinline__ float ex2(float x) {
    float r; asm("ex2.approx.ftz.f32 %0, %1;" : "=f"(r) : "f"(x)); return r;
}
__device__ __forceinline__ float rcpf(float x) {
    float r; asm("rcp.approx.ftz.f32 %0, %1;" : "=f"(r) : "f"(x)); return r;
}
__device__ __forceinline__ uint32_t smem_u32(const void* p) {
    uint32_t a;
    asm("{ .reg .u64 t; cvta.to.shared.u64 t, %1; cvt.u32.u64 %0, t; }" : "=r"(a) : "l"(p));
    return a;
}
/* fp16 m16n8k16 */
__device__ __forceinline__ void mma16h(float* c, const uint32_t* a,
                                       uint32_t b0, uint32_t b1) {
    asm volatile(
        "mma.sync.aligned.m16n8k16.row.col.f32.f16.f16.f32 "
        "{%0,%1,%2,%3},{%4,%5,%6,%7},{%8,%9},{%0,%1,%2,%3};"
        : "+f"(c[0]), "+f"(c[1]), "+f"(c[2]), "+f"(c[3])
        : "r"(a[0]), "r"(a[1]), "r"(a[2]), "r"(a[3]), "r"(b0), "r"(b1));
}
#define CP16(dst, src) \
    asm volatile("cp.async.cg.shared.global [%0], [%1], 16;" :: "r"(dst), "l"(src))
#define CP_COMMIT() asm volatile("cp.async.commit_group;" ::: "memory")
#define CP_WAIT(n)  asm volatile("cp.async.wait_group %0;" :: "n"(n) : "memory")

/* =============== LayerNorm + pair-bias + weight prep =============== */
__global__ void ln_bias_kernel(const float* __restrict__ x,
                               const float* __restrict__ w,
                               const float* __restrict__ b,
                               const float* __restrict__ wb,
                               const float* __restrict__ wq,
                               const float* __restrict__ wk,
                               const float* __restrict__ wv,
                               const float* __restrict__ wg,
                               const float* __restrict__ wo) {
    int row  = blockIdx.x * 8 + (threadIdx.x >> 5);
    int lane = threadIdx.x & 31;
    const float4* xr = (const float4*)(x + (size_t)row * CC);
    float4 v = xr[lane];
    float mu = warp_sum(v.x + v.y + v.z + v.w) * (1.f / 128.f);
    float dx = v.x - mu, dy = v.y - mu, dz = v.z - mu, dw = v.w - mu;
    float var = warp_sum(dx*dx + dy*dy + dz*dz + dw*dw) * (1.f / 128.f);
    float rs = rsqrtf(var + EPSV);
    float4 wv4 = ((const float4*)w)[lane];
    float4 bv = ((const float4*)b)[lane];
    float4 o;
    o.x = dx * rs * wv4.x + bv.x;
    o.y = dy * rs * wv4.y + bv.y;
    o.z = dz * rs * wv4.z + bv.z;
    o.w = dw * rs * wv4.w + bv.w;

    /* store fp16, k-pair permuted (lane holds pairs 2*lane, 2*lane+1) */
    __half2* hr = (__half2*)(g_h + (size_t)row * CC);
    hr[pp8(2*lane)]     = __floats2half2_rn(o.x, o.y);
    hr[pp8(2*lane + 1)] = __floats2half2_rn(o.z, o.w);

    #pragma unroll
    for (int hh = 0; hh < HH; ++hh) {
        float4 wbv = ((const float4*)(wb + hh * CC))[lane];
        float p = o.x*wbv.x + o.y*wbv.y + o.z*wbv.z + o.w*wbv.w;
        p = warp_sum(p);
        if (lane == hh) g_bias[(size_t)hh * PP + row] = p * L2E;
    }

    /* first 64 blocks prep fp16 permuted weights (16384 elems each) */
    if (blockIdx.x < 64) {
        int idx = blockIdx.x * 256 + threadIdx.x;
        int n = idx >> 7, k = idx & 127;
        int d = n * 128 + pp8(k >> 1) * 2 + (k & 1);
        g_wtsh[d]             = __float2half(wq[idx] * SCALE_L2E);
        g_wtsh[16384 + d]     = __float2half(wk[idx]);
        g_wtsh[2*16384 + d]   = __float2half(wv[idx]);
        g_wtsh[3*16384 + d]   = __float2half(wg[idx]);
        g_wtsh[4*16384 + d]   = __float2half(wo[idx]);
    }
}

/* ====== fp16 GEMM: 128x128 tile, 2-stage k64 cp.async, warp 64x32 ======
   GSH = 72 halves (144 B/row): conflict-free 64-bit LDS banks AND
   16-byte aligned rows for cp.async. */
#define GSH 72                         /* smem stride in halves */
#define GAH (128*GSH)                  /* halves per A (or W) region */
#define GSTAGEH (2*GAH)                /* halves per stage */
#define GEMM_SMEM (2 * GSTAGEH * 2)    /* 73728 B */

__global__ void __launch_bounds__(256, 2)
gemm_tc(const __half* __restrict__ Ah, float* __restrict__ OutO, int outp) {
    extern __shared__ __align__(16) char smc[];
    uint32_t sb = smem_u32(smc);
    int wsel = outp ? 4 : (blockIdx.x & 3);
    int m0   = (outp ? blockIdx.x : (blockIdx.x >> 2)) * 128;
    const __half* Wh = g_wtsh + (size_t)wsel * 16384;

    int tid = threadIdx.x;
    int wid = tid >> 5, lane = tid & 31;
    int g = lane >> 2, t = lane & 3;
    int wm = wid >> 2, wn = wid & 3;   /* 2 x 4 warp grid, warp tile 64x32 */

    float acc[4][4][4];
    #pragma unroll
    for (int i = 0; i < 4; ++i)
        #pragma unroll
        for (int j = 0; j < 4; ++j)
            #pragma unroll
            for (int e = 0; e < 4; ++e) acc[i][j][e] = 0.f;

    #define LDCHUNK(c, s) do {                                              \
        uint32_t dA = sb + (uint32_t)((s) * GSTAGEH) * 2;                   \
        uint32_t dW = dA + (uint32_t)GAH * 2;                               \
        _Pragma("unroll")                                                   \
        for (int it = 0; it < 4; ++it) {                                    \
            int idx = tid + it * 256;                                       \
            int r = idx >> 3, ch = idx & 7;                                 \
            CP16(dA + (uint32_t)(r * GSH + ch * 8) * 2,                     \
                 &Ah[(size_t)(m0 + r) * CC + (c) * 64 + ch * 8]);           \
            CP16(dW + (uint32_t)(r * GSH + ch * 8) * 2,                     \
                 &Wh[(size_t)r * CC + (c) * 64 + ch * 8]);                  \
        }                                                                   \
    } while (0)

    #define COMPUTE(s) do {                                                 \
        const __half* As = (const __half*)smc + (s) * GSTAGEH;              \
        const __half* Ws = As + GAH;                                        \
        _Pragma("unroll")                                                   \
        for (int kk = 0; kk < 4; ++kk) {                                    \
            uint32_t af[4][4];                                              \
            _Pragma("unroll")                                               \
            for (int mt = 0; mt < 4; ++mt) {                                \
                uint2 u0 = *(const uint2*)&As[(wm*64 + mt*16 + g) * GSH + kk*16 + 4*t]; \
                uint2 u1 = *(const uint2*)&As[(wm*64 + mt*16 + g + 8) * GSH + kk*16 + 4*t]; \
                af[mt][0] = u0.x; af[mt][1] = u1.x;                         \
                af[mt][2] = u0.y; af[mt][3] = u1.y;                         \
            }                                                               \
            _Pragma("unroll")                                               \
            for (int nt = 0; nt < 4; ++nt) {                                \
                uint2 z = *(const uint2*)&Ws[(wn*32 + nt*8 + g) * GSH + kk*16 + 4*t]; \
                _Pragma("unroll")                                           \
                for (int mt = 0; mt < 4; ++mt)                              \
                    mma16h(acc[mt][nt], af[mt], z.x, z.y);                  \
            }                                                               \
        }                                                                   \
    } while (0)

    LDCHUNK(0, 0); CP_COMMIT();
    LDCHUNK(1, 1); CP_COMMIT();
    CP_WAIT(1); __syncthreads();
    COMPUTE(0);
    CP_WAIT(0); __syncthreads();
    COMPUTE(1);

    /* epilogue */
    #pragma unroll
    for (int mt = 0; mt < 4; ++mt) {
        int row0 = m0 + wm*64 + mt*16 + g;
        #pragma unroll
        for (int nt = 0; nt < 4; ++nt) {
            float a0 = acc[mt][nt][0], a1 = acc[mt][nt][1];
            float a2 = acc[mt][nt][2], a3 = acc[mt][nt][3];
            int coln = wn*32 + nt*8 + 2*t;           /* natural col */
            int ppi  = pp8(wn*16 + 4*nt + t);        /* permuted pair idx */
            size_t i0n = (size_t)row0 * CC;
            size_t i1n = (size_t)(row0 + 8) * CC;
            if (outp) {
                *(float2*)&OutO[i0n + coln] = make_float2(a0, a1);
                *(float2*)&OutO[i1n + coln] = make_float2(a2, a3);
            } else if (wsel == 0) {
                *(__half2*)&g_qh[i0n + ppi*2] = __floats2half2_rn(a0, a1);
                *(__half2*)&g_qh[i1n + ppi*2] = __floats2half2_rn(a2, a3);
            } else if (wsel == 1) {
                *(__half2*)&g_kh[i0n + ppi*2] = __floats2half2_rn(a0, a1);
                *(__half2*)&g_kh[i1n + ppi*2] = __floats2half2_rn(a2, a3);
            } else if (wsel == 2) {
                *(__half2*)&g_vh[i0n + coln] = __floats2half2_rn(a0, a1);
                *(__half2*)&g_vh[i1n + coln] = __floats2half2_rn(a2, a3);
            } else {
                float s0 = rcpf(1.f + ex2(-a0 * L2E));
                float s1 = rcpf(1.f + ex2(-a1 * L2E));
                float s2 = rcpf(1.f + ex2(-a2 * L2E));
                float s3 = rcpf(1.f + ex2(-a3 * L2E));
                *(float2*)&g_g[i0n + coln] = make_float2(s0, s1);
                *(float2*)&g_g[i1n + coln] = make_float2(s2, s3);
            }
        }
    }
    #undef LDCHUNK
    #undef COMPUTE
}

/* =============== attention: fp16 scores + fp16 2-term PV ==================
   block=(i,h); 8 warps x 32 q-rows; 8 k-chunks of 32.
   KSTH = 40 halves (80 B/row): conflict-free 64-bit LDS banks, rows
   16-byte aligned for cp.async. */
#define KSTH 40
#define KBYTES (256*KSTH*2)       /* 20480 */
#define VTP 136
#define ATTN_SMEM (2*KBYTES)      /* 40960 B */

__global__ void __launch_bounds__(256, 2) attn_tc() {
    extern __shared__ __align__(16) char smc[];
    uint32_t sb = smem_u32(smc);
    __half* Ksm = (__half*)smc;
    __half* Usm = (__half*)(smc + KBYTES);   /* Q stage, then Vt */
    int tid = threadIdx.x;
    int wid = tid >> 5, lane = tid & 31;
    int g = lane >> 2, t = lane & 3;
    int i = blockIdx.x, h = blockIdx.y;
    size_t base = ((size_t)i * SS) * CC + (size_t)h * 32;

    /* stage 1: cp.async K and Q rows (64 B each) */
    {
        int r = tid;
        uint32_t kd = sb + (uint32_t)(r * KSTH) * 2;
        uint32_t qd = sb + (uint32_t)KBYTES + (uint32_t)(r * KSTH) * 2;
        const __half* ks = &g_kh[base + (size_t)r * CC];
        const __half* qs = &g_qh[base + (size_t)r * CC];
        #pragma unroll
        for (int ch = 0; ch < 4; ++ch) {
            CP16(kd + ch * 16, ks + ch * 8);
            CP16(qd + ch * 16, qs + ch * 8);
        }
        CP_COMMIT();
    }
    /* V row to registers (natural layout) */
    unsigned short sv[32];
    {
        const uint4* vg = (const uint4*)(g_vh + base + (size_t)tid * CC);
        *(uint4*)&sv[0]  = vg[0];
        *(uint4*)&sv[8]  = vg[1];
        *(uint4*)&sv[16] = vg[2];
        *(uint4*)&sv[24] = vg[3];
    }
    CP_WAIT(0);
    __syncthreads();

    /* stage 2: Q fragments to registers (2 m-tiles, 2 k16-groups) */
    int wrow = wid * 32;
    uint32_t qa[2][2][4];
    #pragma unroll
    for (int mt = 0; mt < 2; ++mt)
        #pragma unroll
        for (int kk = 0; kk < 2; ++kk) {
            uint2 u0 = *(const uint2*)&Usm[(wrow + mt*16 + g) * KSTH + kk*16 + 4*t];
            uint2 u1 = *(const uint2*)&Usm[(wrow + mt*16 + g + 8) * KSTH + kk*16 + 4*t];
            qa[mt][kk][0] = u0.x; qa[mt][kk][1] = u1.x;
            qa[mt][kk][2] = u0.y; qa[mt][kk][3] = u1.y;
        }
    __syncthreads();

    /* stage 3: Vt fp16 in U region, kseq-pair-permuted */
    {
        unsigned short* vt = (unsigned short*)Usm;
        int pr = tid >> 1, hs = tid & 1;
        int ppr = (pr & ~7) | ((pr & 3) * 2 + ((pr >> 2) & 1));
        #pragma unroll
        for (int d = 0; d < 32; ++d)
            vt[(d * VTP + ppr) * 2 + hs] = sv[d];
    }
    __syncthreads();

    const uint32_t* vtw = (const uint32_t*)Usm;
    const float* bh = g_bias + (size_t)h * PP;

    float pv[2][4][4];
    #pragma unroll
    for (int mt = 0; mt < 2; ++mt)
        #pragma unroll
        for (int nt = 0; nt < 4; ++nt)
            #pragma unroll
            for (int e = 0; e < 4; ++e) pv[mt][nt][e] = 0.f;
    float lsum[2][2] = {{0.f,0.f},{0.f,0.f}};

    for (int c = 0; c < 8; ++c) {
        /* scores (fp16 k16): 32 j x 32 k */
        float sacc[2][4][4];
        #pragma unroll
        for (int mt = 0; mt < 2; ++mt)
            #pragma unroll
            for (int nt = 0; nt < 4; ++nt)
                #pragma unroll
                for (int e = 0; e < 4; ++e) sacc[mt][nt][e] = 0.f;
        #pragma unroll
        for (int nt = 0; nt < 4; ++nt)
            #pragma unroll
            for (int kk = 0; kk < 2; ++kk) {
                uint2 z = *(const uint2*)&Ksm[(c*32 + nt*8 + g) * KSTH + kk*16 + 4*t];
                mma16h(sacc[0][nt], qa[0][kk], z.x, z.y);
                mma16h(sacc[1][nt], qa[1][kk], z.x, z.y);
            }

        /* softmax + pack P hi/lo fp16 A-fragments */
        uint32_t ah[2][2][4], al[2][2][4];
        #pragma unroll
        for (int mt = 0; mt < 2; ++mt) {
            int j = wrow + mt*16 + g;
            #pragma unroll
            for (int kk2 = 0; kk2 < 2; ++kk2)
                #pragma unroll
                for (int qn = 0; qn < 2; ++qn) {
                    int nt = kk2*2 + qn;
                    int kcol = c*32 + nt*8 + 2*t;
                    float2 b0 = *(const float2*)&bh[(size_t)j * SS + kcol];
                    float2 b1 = *(const float2*)&bh[(size_t)(j+8) * SS + kcol];
                    float p0 = ex2(sacc[mt][nt][0] + b0.x);
                    float p1 = ex2(sacc[mt][nt][1] + b0.y);
                    float p2 = ex2(sacc[mt][nt][2] + b1.x);
                    float p3 = ex2(sacc[mt][nt][3] + b1.y);
                    lsum[mt][0] += p0 + p1;
                    lsum[mt][1] += p2 + p3;
                    __half2 H01 = __floats2half2_rn(p0, p1);
                    __half2 H23 = __floats2half2_rn(p2, p3);
                    ah[mt][kk2][qn*2+0] = *(uint32_t*)&H01;
                    ah[mt][kk2][qn*2+1] = *(uint32_t*)&H23;
                    __half2 L01 = __floats2half2_rn(p0 - __low2float(H01),
                                                    p1 - __high2float(H01));
                    __half2 L23 = __floats2half2_rn(p2 - __low2float(H23),
                                                    p3 - __high2float(H23));
                    al[mt][kk2][qn*2+0] = *(uint32_t*)&L01;
                    al[mt][kk2][qn*2+1] = *(uint32_t*)&L23;
                }
        }

        /* PV (fp16 k16, 2 terms), V fragments shared across both m-tiles */
        #pragma unroll
        for (int kk2 = 0; kk2 < 2; ++kk2)
            #pragma unroll
            for (int nt = 0; nt < 4; ++nt) {
                uint2 b = *(const uint2*)&vtw[(nt*8 + g) * VTP + c*16 + kk2*8 + 2*t];
                #pragma unroll
                for (int mt = 0; mt < 2; ++mt) {
                    mma16h(pv[mt][nt], ah[mt][kk2], b.x, b.y);
                    mma16h(pv[mt][nt], al[mt][kk2], b.x, b.y);
                }
            }
    }

    /* reduce l over quad lanes, gate, store fp16 permuted into g_oh */
    float inv[2][2];
    #pragma unroll
    for (int mt = 0; mt < 2; ++mt)
        #pragma unroll
        for (int rh = 0; rh < 2; ++rh) {
            float l = lsum[mt][rh];
            l += __shfl_xor_sync(0xffffffffu, l, 1);
            l += __shfl_xor_sync(0xffffffffu, l, 2);
            inv[mt][rh] = rcpf(l);
        }
    #pragma unroll
    for (int mt = 0; mt < 2; ++mt) {
        int j = wrow + mt*16 + g;
        size_t r0 = base + (size_t)j * CC;
        size_t r1 = base + (size_t)(j+8) * CC;
        #pragma unroll
        for (int nt = 0; nt < 4; ++nt) {
            int col = nt*8 + 2*t;                 /* within-head natural */
            int ppi = pp8(4*nt + t);              /* within-head permuted pair */
            float2 s0 = *(const float2*)&g_g[r0 + col];
            float2 s1 = *(const float2*)&g_g[r1 + col];
            *(__half2*)&g_oh[r0 + ppi*2] =
                __floats2half2_rn(pv[mt][nt][0]*inv[mt][0]*s0.x,
                                  pv[mt][nt][1]*inv[mt][0]*s0.y);
            *(__half2*)&g_oh[r1 + ppi*2] =
                __floats2half2_rn(pv[mt][nt][2]*inv[mt][1]*s1.x,
                                  pv[mt][nt][3]*inv[mt][1]*s1.y);
        }
    }
}

extern "C" void kernel_launch(void* const* d_in, const int* in_sizes, int n_in,
                              void* d_out, int out_size) {
    (void)in_sizes; (void)n_in; (void)out_size;
    const float* x      = (const float*)d_in[0];
    const float* ln_w   = (const float*)d_in[1];
    const float* ln_b   = (const float*)d_in[2];
    const float* w_bias = (const float*)d_in[3];
    const float* w_q    = (const float*)d_in[4];
    const float* w_k    = (const float*)d_in[5];
    const float* w_v    = (const float*)d_in[6];
    const float* w_g    = (const float*)d_in[7];
    const float* w_o    = (const float*)d_in[8];
    float* out = (float*)d_out;

    __half *ph, *po;
    cudaGetSymbolAddress((void**)&ph, g_h);
    cudaGetSymbolAddress((void**)&po, g_oh);

    cudaFuncSetAttribute(gemm_tc,
                         cudaFuncAttributeMaxDynamicSharedMemorySize, GEMM_SMEM);
    cudaFuncSetAttribute(attn_tc,
                         cudaFuncAttributeMaxDynamicSharedMemorySize, ATTN_SMEM);

    ln_bias_kernel<<<PP/8, 256>>>(x, ln_w, ln_b, w_bias,
                                  w_q, w_k, w_v, w_g, w_o);

    /* fused q,k,v,g projections; wsel = blockIdx.x & 3 (A tiles L2-shared) */
    gemm_tc<<<(PP/128) * 4, 256, GEMM_SMEM>>>(ph, nullptr, 0);

    attn_tc<<<dim3(SS, HH), 256, ATTN_SMEM>>>();

    /* output projection (o already gated, fp16 permuted) */
    gemm_tc<<<PP/128, 256, GEMM_SMEM>>>(po, out, 1);
}